// round 2
// baseline (speedup 1.0000x reference)
#include <cuda_runtime.h>
#include <cuda_fp16.h>

#define B_   64
#define P_   2304
#define D1_  16
#define S_   32
#define D2_  32
#define SD_  1024          // S_*D2_
#define EPSQ 1e-7f

// ---------------- scratch (device globals: allocation-free) ----------------
__device__ float  g_u[P_ * D1_ * B_];                 // [p][k][b]
__device__ __half g_preds[(size_t)P_ * SD_ * B_];     // [p][s*32+d][b]  (302 MB)
__device__ float  g_ws[SD_ * B_];                     // [sd][b]
__device__ float  g_v [SD_ * B_];                     // [sd][b]
__device__ float  g_logits[P_ * S_];                  // [p][s]
__device__ float  g_rw    [P_ * S_];                  // [p][s]

// ---------------- tiny init kernels ----------------
__global__ void zero_logits_kernel() {
    int i = blockIdx.x * blockDim.x + threadIdx.x;
    if (i < P_ * S_) g_logits[i] = 0.f;
}
__global__ void zero_ws_kernel() {
    int i = blockIdx.x * blockDim.x + threadIdx.x;
    g_ws[i] = 0.f;                                    // grid covers exactly SD_*B_
}

// ---------------- 1) u = squash(caps1_raw) over D1, transposed to [p][k][b] ----------------
__global__ void squash_u_kernel(const float* __restrict__ caps) {
    int gid = blockIdx.x * blockDim.x + threadIdx.x;  // 0 .. B_*P_-1, gid = b*P_+p
    const float4* src = (const float4*)(caps + (size_t)gid * 16);
    float4 a0 = src[0], a1 = src[1], a2 = src[2], a3 = src[3];
    float x[16] = {a0.x,a0.y,a0.z,a0.w, a1.x,a1.y,a1.z,a1.w,
                   a2.x,a2.y,a2.z,a2.w, a3.x,a3.y,a3.z,a3.w};
    float sq = 0.f;
    #pragma unroll
    for (int k = 0; k < 16; k++) sq += x[k] * x[k];
    float sc = (sq / (1.f + sq)) / sqrtf(sq + EPSQ);
    int b = gid / P_, p = gid % P_;
    float* dst = g_u + (size_t)p * (D1_ * B_) + b;
    #pragma unroll
    for (int k = 0; k < 16; k++) dst[k * B_] = x[k] * sc;
}

// ---------------- 2) preds[p][sd][b] = sum_k W[p][sd][k] * u[p][k][b]  (fp16 store) ----------------
__global__ void __launch_bounds__(256) preds_kernel(const float* __restrict__ W) {
    __shared__ float sW[512 * 17];    // half of W[p], padded rows (bank-conflict-free)
    __shared__ float sU[16 * 64];     // u[p][k][b]
    int p = blockIdx.x, tid = threadIdx.x;

    { // load u tile (1024 floats)
        const float4* up = (const float4*)(g_u + (size_t)p * (D1_ * B_));
        ((float4*)sU)[tid] = up[tid];
    }
    const float* Wp = W + (size_t)p * (SD_ * D1_);
    int tb  = tid & 7;    // b-group: owns b = tb*8 .. tb*8+7
    int tsd = tid >> 3;   // 0..31

    for (int h = 0; h < 2; h++) {
        __syncthreads();
        const float4* wp4 = (const float4*)(Wp + h * 8192);
        #pragma unroll
        for (int t = 0; t < 8; t++) {
            int q = tid + 256 * t;            // float4 index 0..2047
            float4 w = wp4[q];
            int r = q >> 2;                   // row 0..511
            int k = (q & 3) * 4;
            float* d = &sW[r * 17 + k];
            d[0] = w.x; d[1] = w.y; d[2] = w.z; d[3] = w.w;
        }
        __syncthreads();

        #pragma unroll
        for (int j = 0; j < 2; j++) {
            int rb = (j * 32 + tsd) * 8;      // local row base 0..504
            float acc[8][8];
            #pragma unroll
            for (int i = 0; i < 8; i++)
                #pragma unroll
                for (int jj = 0; jj < 8; jj++) acc[i][jj] = 0.f;

            #pragma unroll
            for (int k = 0; k < 16; k++) {
                float wv[8], uv[8];
                #pragma unroll
                for (int i = 0; i < 8; i++)  wv[i]  = sW[(rb + i) * 17 + k];
                #pragma unroll
                for (int jj = 0; jj < 8; jj++) uv[jj] = sU[k * 64 + tb * 8 + jj];
                #pragma unroll
                for (int i = 0; i < 8; i++)
                    #pragma unroll
                    for (int jj = 0; jj < 8; jj++) acc[i][jj] += wv[i] * uv[jj];
            }
            #pragma unroll
            for (int i = 0; i < 8; i++) {
                __half2 h0 = __floats2half2_rn(acc[i][0], acc[i][1]);
                __half2 h1 = __floats2half2_rn(acc[i][2], acc[i][3]);
                __half2 h2 = __floats2half2_rn(acc[i][4], acc[i][5]);
                __half2 h3 = __floats2half2_rn(acc[i][6], acc[i][7]);
                uint4 o;
                o.x = *(const unsigned*)&h0; o.y = *(const unsigned*)&h1;
                o.z = *(const unsigned*)&h2; o.w = *(const unsigned*)&h3;
                size_t off = (size_t)p * (SD_ * B_) + (size_t)(h * 512 + rb + i) * B_ + tb * 8;
                *(uint4*)(g_preds + off) = o;  // 16B-aligned
            }
        }
    }
}

// ---------------- 3) rw[p][s] = softmax_s(logits[p][s]) ----------------
__global__ void softmax_kernel() {
    int p    = blockIdx.x * 8 + (threadIdx.x >> 5);
    int lane = threadIdx.x & 31;
    float x = g_logits[p * S_ + lane];
    float m = x;
    #pragma unroll
    for (int o = 16; o; o >>= 1) m = fmaxf(m, __shfl_xor_sync(0xffffffffu, m, o));
    float e = expf(x - m);
    float sum = e;
    #pragma unroll
    for (int o = 16; o; o >>= 1) sum += __shfl_xor_sync(0xffffffffu, sum, o);
    g_rw[p * S_ + lane] = e / sum;
}

// ---------------- 4) ws[sd][b] = sum_p rw[p][s] * preds[p][sd][b]  (streaming) ----------------
__global__ void ws_kernel() {
    int sd = blockIdx.x;
    int s  = sd >> 5;
    int b  = threadIdx.x;
    const int CP = P_ / 8;                 // 288 p's per chunk
    int p0 = blockIdx.y * CP;
    const __half* pp = g_preds + (size_t)p0 * (SD_ * B_) + (size_t)sd * B_ + b;
    float acc = 0.f;
    #pragma unroll 8
    for (int i = 0; i < CP; i++) {
        float w = __ldg(&g_rw[(p0 + i) * S_ + s]);
        acc += w * __half2float(__ldg(pp + (size_t)i * (SD_ * B_)));
    }
    atomicAdd(&g_ws[sd * B_ + b], acc);
}

// ---------------- 5) v = squash(ws) over D2 ----------------
__global__ void squash_v_kernel() {
    int gid = blockIdx.x * blockDim.x + threadIdx.x;   // 0..2047
    int s = gid >> 6, b = gid & 63;
    float x[32]; float sq = 0.f;
    #pragma unroll
    for (int d = 0; d < 32; d++) { x[d] = g_ws[(s * 32 + d) * B_ + b]; sq += x[d] * x[d]; }
    float sc = (sq / (1.f + sq)) / sqrtf(sq + EPSQ);
    #pragma unroll
    for (int d = 0; d < 32; d++) g_v[(s * 32 + d) * B_ + b] = x[d] * sc;
}

// ---------------- 6) logits[p][s] += (1/B) sum_{d,b} preds[p][s,d,b] * v[s,d,b] ----------------
__global__ void agree_kernel() {
    int p    = blockIdx.x;
    int warp = threadIdx.x >> 5, lane = threadIdx.x & 31;
    #pragma unroll
    for (int si = 0; si < 4; si++) {
        int s = si * 8 + warp;
        const __half2* pp = (const __half2*)(g_preds + ((size_t)p * SD_ + s * D2_) * B_);
        const float2*  vp = (const float2*)(g_v + (size_t)(s * D2_) * B_);
        float acc = 0.f;
        #pragma unroll 8
        for (int d = 0; d < 32; d++) {
            float2 hf = __half22float2(__ldg(pp + d * 32 + lane));
            float2 vv = __ldg(vp + d * 32 + lane);
            acc += hf.x * vv.x + hf.y * vv.y;
        }
        #pragma unroll
        for (int o = 16; o; o >>= 1) acc += __shfl_xor_sync(0xffffffffu, acc, o);
        if (lane == 0) g_logits[p * S_ + s] += acc * (1.f / 64.f);
    }
}

// ---------------- 7) out[b][s][d] = squash(ws) over D2 ----------------
__global__ void final_kernel(float* __restrict__ out) {
    int gid = blockIdx.x * blockDim.x + threadIdx.x;
    int s = gid >> 6, b = gid & 63;
    float x[32]; float sq = 0.f;
    #pragma unroll
    for (int d = 0; d < 32; d++) { x[d] = g_ws[(s * 32 + d) * B_ + b]; sq += x[d] * x[d]; }
    float sc = (sq / (1.f + sq)) / sqrtf(sq + EPSQ);
    #pragma unroll
    for (int d = 0; d < 32; d++) out[(b * 32 + s) * 32 + d] = x[d] * sc;
}

// ---------------- launch ----------------
extern "C" void kernel_launch(void* const* d_in, const int* in_sizes, int n_in,
                              void* d_out, int out_size) {
    const float* caps = (const float*)d_in[0];   // [B,P,D1] fp32
    const float* W    = (const float*)d_in[1];   // [P,S,D2,D1] fp32
    float* out        = (float*)d_out;           // [B,1,S,D2,1] fp32

    zero_logits_kernel<<<(P_ * S_) / 256, 256>>>();
    squash_u_kernel<<<(B_ * P_) / 256, 256>>>(caps);
    preds_kernel<<<P_, 256>>>(W);

    for (int it = 0; it < 3; it++) {
        softmax_kernel<<<P_ / 8, 256>>>();
        zero_ws_kernel<<<(SD_ * B_) / 256, 256>>>();
        ws_kernel<<<dim3(SD_, 8), B_>>>();
        if (it < 2) {
            squash_v_kernel<<<8, 256>>>();
            agree_kernel<<<P_, 256>>>();
        } else {
            final_kernel<<<8, 256>>>(out);
        }
    }
}

// round 3
// speedup vs baseline: 1.0026x; 1.0026x over previous
#include <cuda_runtime.h>
#include <cuda_fp16.h>

#define B_   64
#define P_   2304
#define D1_  16
#define S_   32
#define D2_  32
#define SD_  1024          // S_*D2_
#define EPSQ 1e-7f

// ---------------- scratch (device globals: allocation-free) ----------------
__device__ float  g_u[P_ * D1_ * B_];                 // [p][k][b]
__device__ __half g_preds[(size_t)P_ * SD_ * B_];     // [p][s*32+d][b]  (302 MB)
__device__ float  g_ws[SD_ * B_];                     // [sd][b]
__device__ float  g_v [SD_ * B_];                     // [sd][b]
__device__ float  g_logits[P_ * S_];                  // [p][s]
__device__ float  g_rw    [P_ * S_];                  // [p][s]

// ---------------- tiny init kernels ----------------
__global__ void zero_logits_kernel() {
    int i = blockIdx.x * blockDim.x + threadIdx.x;
    if (i < P_ * S_) g_logits[i] = 0.f;
}
__global__ void zero_ws_kernel() {
    int i = blockIdx.x * blockDim.x + threadIdx.x;
    g_ws[i] = 0.f;                                    // grid covers exactly SD_*B_
}

// ---------------- 1) u = squash(caps1_raw) over D1, transposed to [p][k][b] ----------------
__global__ void squash_u_kernel(const float* __restrict__ caps) {
    int gid = blockIdx.x * blockDim.x + threadIdx.x;  // 0 .. B_*P_-1, gid = b*P_+p
    const float4* src = (const float4*)(caps + (size_t)gid * 16);
    float4 a0 = src[0], a1 = src[1], a2 = src[2], a3 = src[3];
    float x[16] = {a0.x,a0.y,a0.z,a0.w, a1.x,a1.y,a1.z,a1.w,
                   a2.x,a2.y,a2.z,a2.w, a3.x,a3.y,a3.z,a3.w};
    float sq = 0.f;
    #pragma unroll
    for (int k = 0; k < 16; k++) sq += x[k] * x[k];
    float sc = (sq / (1.f + sq)) / sqrtf(sq + EPSQ);
    int b = gid / P_, p = gid % P_;
    float* dst = g_u + (size_t)p * (D1_ * B_) + b;
    #pragma unroll
    for (int k = 0; k < 16; k++) dst[k * B_] = x[k] * sc;
}

// ---------------- 2) preds[p][sd][b] = sum_k W[p][sd][k] * u[p][k][b]  (fp16 store) ----------------
__global__ void __launch_bounds__(256) preds_kernel(const float* __restrict__ W) {
    __shared__ float sW[512 * 17];    // half of W[p], padded rows (bank-conflict-free)
    __shared__ float sU[16 * 64];     // u[p][k][b]
    int p = blockIdx.x, tid = threadIdx.x;

    { // load u tile (1024 floats)
        const float4* up = (const float4*)(g_u + (size_t)p * (D1_ * B_));
        ((float4*)sU)[tid] = up[tid];
    }
    const float* Wp = W + (size_t)p * (SD_ * D1_);
    int tb  = tid & 7;    // b-group: owns b = tb*8 .. tb*8+7
    int tsd = tid >> 3;   // 0..31

    for (int h = 0; h < 2; h++) {
        __syncthreads();
        const float4* wp4 = (const float4*)(Wp + h * 8192);
        #pragma unroll
        for (int t = 0; t < 8; t++) {
            int q = tid + 256 * t;            // float4 index 0..2047
            float4 w = wp4[q];
            int r = q >> 2;                   // row 0..511
            int k = (q & 3) * 4;
            float* d = &sW[r * 17 + k];
            d[0] = w.x; d[1] = w.y; d[2] = w.z; d[3] = w.w;
        }
        __syncthreads();

        #pragma unroll
        for (int j = 0; j < 2; j++) {
            int rb = (j * 32 + tsd) * 8;      // local row base 0..504
            float acc[8][8];
            #pragma unroll
            for (int i = 0; i < 8; i++)
                #pragma unroll
                for (int jj = 0; jj < 8; jj++) acc[i][jj] = 0.f;

            #pragma unroll
            for (int k = 0; k < 16; k++) {
                float wv[8], uv[8];
                #pragma unroll
                for (int i = 0; i < 8; i++)  wv[i]  = sW[(rb + i) * 17 + k];
                #pragma unroll
                for (int jj = 0; jj < 8; jj++) uv[jj] = sU[k * 64 + tb * 8 + jj];
                #pragma unroll
                for (int i = 0; i < 8; i++)
                    #pragma unroll
                    for (int jj = 0; jj < 8; jj++) acc[i][jj] += wv[i] * uv[jj];
            }
            #pragma unroll
            for (int i = 0; i < 8; i++) {
                __half2 h0 = __floats2half2_rn(acc[i][0], acc[i][1]);
                __half2 h1 = __floats2half2_rn(acc[i][2], acc[i][3]);
                __half2 h2 = __floats2half2_rn(acc[i][4], acc[i][5]);
                __half2 h3 = __floats2half2_rn(acc[i][6], acc[i][7]);
                uint4 o;
                o.x = *(const unsigned*)&h0; o.y = *(const unsigned*)&h1;
                o.z = *(const unsigned*)&h2; o.w = *(const unsigned*)&h3;
                size_t off = (size_t)p * (SD_ * B_) + (size_t)(h * 512 + rb + i) * B_ + tb * 8;
                *(uint4*)(g_preds + off) = o;  // 16B-aligned
            }
        }
    }
}

// ---------------- 3) rw[p][s] = softmax_s(logits[p][s]) ----------------
__global__ void softmax_kernel() {
    int p    = blockIdx.x * 8 + (threadIdx.x >> 5);
    int lane = threadIdx.x & 31;
    float x = g_logits[p * S_ + lane];
    float m = x;
    #pragma unroll
    for (int o = 16; o; o >>= 1) m = fmaxf(m, __shfl_xor_sync(0xffffffffu, m, o));
    float e = expf(x - m);
    float sum = e;
    #pragma unroll
    for (int o = 16; o; o >>= 1) sum += __shfl_xor_sync(0xffffffffu, sum, o);
    g_rw[p * S_ + lane] = e / sum;
}

// ---------------- 4) ws[sd][b] = sum_p rw[p][s] * preds[p][sd][b]  (streaming) ----------------
__global__ void ws_kernel() {
    int sd = blockIdx.x;
    int s  = sd >> 5;
    int b  = threadIdx.x;
    const int CP = P_ / 8;                 // 288 p's per chunk
    int p0 = blockIdx.y * CP;
    const __half* pp = g_preds + (size_t)p0 * (SD_ * B_) + (size_t)sd * B_ + b;
    float acc = 0.f;
    #pragma unroll 8
    for (int i = 0; i < CP; i++) {
        float w = __ldg(&g_rw[(p0 + i) * S_ + s]);
        acc += w * __half2float(__ldg(pp + (size_t)i * (SD_ * B_)));
    }
    atomicAdd(&g_ws[sd * B_ + b], acc);
}

// ---------------- 5) v = squash(ws) over D2 ----------------
__global__ void squash_v_kernel() {
    int gid = blockIdx.x * blockDim.x + threadIdx.x;   // 0..2047
    int s = gid >> 6, b = gid & 63;
    float x[32]; float sq = 0.f;
    #pragma unroll
    for (int d = 0; d < 32; d++) { x[d] = g_ws[(s * 32 + d) * B_ + b]; sq += x[d] * x[d]; }
    float sc = (sq / (1.f + sq)) / sqrtf(sq + EPSQ);
    #pragma unroll
    for (int d = 0; d < 32; d++) g_v[(s * 32 + d) * B_ + b] = x[d] * sc;
}

// ---------------- 6) logits[p][s] += (1/B) sum_{d,b} preds[p][s,d,b] * v[s,d,b] ----------------
__global__ void agree_kernel() {
    int p    = blockIdx.x;
    int warp = threadIdx.x >> 5, lane = threadIdx.x & 31;
    #pragma unroll
    for (int si = 0; si < 4; si++) {
        int s = si * 8 + warp;
        const __half2* pp = (const __half2*)(g_preds + ((size_t)p * SD_ + s * D2_) * B_);
        const float2*  vp = (const float2*)(g_v + (size_t)(s * D2_) * B_);
        float acc = 0.f;
        #pragma unroll 8
        for (int d = 0; d < 32; d++) {
            float2 hf = __half22float2(__ldg(pp + d * 32 + lane));
            float2 vv = __ldg(vp + d * 32 + lane);
            acc += hf.x * vv.x + hf.y * vv.y;
        }
        #pragma unroll
        for (int o = 16; o; o >>= 1) acc += __shfl_xor_sync(0xffffffffu, acc, o);
        if (lane == 0) g_logits[p * S_ + s] += acc * (1.f / 64.f);
    }
}

// ---------------- 7) out[b][s][d] = squash(ws) over D2 ----------------
__global__ void final_kernel(float* __restrict__ out) {
    int gid = blockIdx.x * blockDim.x + threadIdx.x;
    int s = gid >> 6, b = gid & 63;
    float x[32]; float sq = 0.f;
    #pragma unroll
    for (int d = 0; d < 32; d++) { x[d] = g_ws[(s * 32 + d) * B_ + b]; sq += x[d] * x[d]; }
    float sc = (sq / (1.f + sq)) / sqrtf(sq + EPSQ);
    #pragma unroll
    for (int d = 0; d < 32; d++) out[(b * 32 + s) * 32 + d] = x[d] * sc;
}

// ---------------- launch ----------------
extern "C" void kernel_launch(void* const* d_in, const int* in_sizes, int n_in,
                              void* d_out, int out_size) {
    const float* caps = (const float*)d_in[0];   // [B,P,D1] fp32
    const float* W    = (const float*)d_in[1];   // [P,S,D2,D1] fp32
    float* out        = (float*)d_out;           // [B,1,S,D2,1] fp32

    zero_logits_kernel<<<(P_ * S_) / 256, 256>>>();
    squash_u_kernel<<<(B_ * P_) / 256, 256>>>(caps);
    preds_kernel<<<P_, 256>>>(W);

    for (int it = 0; it < 3; it++) {
        softmax_kernel<<<P_ / 8, 256>>>();
        zero_ws_kernel<<<(SD_ * B_) / 256, 256>>>();
        ws_kernel<<<dim3(SD_, 8), B_>>>();
        if (it < 2) {
            squash_v_kernel<<<8, 256>>>();
            agree_kernel<<<P_, 256>>>();
        } else {
            final_kernel<<<8, 256>>>(out);
        }
    }
}

// round 6
// speedup vs baseline: 1.6612x; 1.6569x over previous
#include <cuda_runtime.h>
#include <cuda_fp16.h>
#include <cstdint>

#define B_   64
#define P_   2304
#define D1_  16
#define S_   32
#define D2_  32
#define SD_  1024
#define EPSQ 1e-7f

// streaming loads (evict-first): preds has zero reuse within a pass
__device__ __forceinline__ float2 ldcs_h2(const __half2* p) {
    unsigned v;
    asm volatile("ld.global.cs.b32 %0, [%1];" : "=r"(v) : "l"(p));
    return __half22float2(*(__half2*)&v);
}

// ---------------- scratch ----------------
__device__ __half g_uh[P_ * B_ * D1_];               // [p][b][k] fp16
__device__ __half g_preds[(size_t)P_ * SD_ * B_];    // [p][sd][b] fp16 (302 MB)
__device__ float  g_ws[SD_ * B_];
__device__ float  g_v [SD_ * B_];
__device__ float  g_logits[P_ * S_];
__device__ float  g_rw    [P_ * S_];

// ---------------- tiny kernels ----------------
__global__ void zero_logits_kernel() {
    int i = blockIdx.x * blockDim.x + threadIdx.x;
    if (i < P_ * S_) g_logits[i] = 0.f;
}
__global__ void zero_ws_kernel() {
    int i = blockIdx.x * blockDim.x + threadIdx.x;
    g_ws[i] = 0.f;
}

// ---------------- u = squash(caps) over D1 -> g_uh[p][b][k] fp16 ----------------
__global__ void squash_u_kernel(const float* __restrict__ caps) {
    int gid = blockIdx.x * blockDim.x + threadIdx.x;   // p*64+b
    int p = gid >> 6, b = gid & 63;
    const float4* src = (const float4*)(caps + ((size_t)b * P_ + p) * 16);
    float4 a0 = src[0], a1 = src[1], a2 = src[2], a3 = src[3];
    float x[16] = {a0.x,a0.y,a0.z,a0.w, a1.x,a1.y,a1.z,a1.w,
                   a2.x,a2.y,a2.z,a2.w, a3.x,a3.y,a3.z,a3.w};
    float sq = 0.f;
    #pragma unroll
    for (int k = 0; k < 16; k++) sq += x[k] * x[k];
    float sc = (sq / (1.f + sq)) / sqrtf(sq + EPSQ);
    __half h[16];
    #pragma unroll
    for (int k = 0; k < 16; k++) h[k] = __float2half(x[k] * sc);
    uint4* dst = (uint4*)(g_uh + (size_t)gid * 16);
    dst[0] = ((uint4*)h)[0];
    dst[1] = ((uint4*)h)[1];
}

// ---------------- preds via mma.sync (HMMA): preds_p = W_p @ u_p^T ----------------
// m16n8k16.row.col: A row-major (k-contig) = W[sd][k]; B col-major (k-contig) = u[b][k].
// Per CTA (p): 8 warps x 8 row-tiles x (16 rows x 64 cols). Single K=16 step.
#define ST_PITCH 72   // halves; bank = (4r+q) mod 32 -> conflict-free half2 stores

__global__ void __launch_bounds__(256) preds_hmma_kernel(const float* __restrict__ W) {
    __shared__ __align__(16) __half st[8][16 * ST_PITCH];  // per-warp staging (18.4 KB)
    int tid = threadIdx.x, wid = tid >> 5, lane = tid & 31;
    int p = blockIdx.x;
    int r = lane >> 2;      // groupID 0..7
    int q = lane & 3;

    // B fragments: 8 col-tiles, loaded once (u is tiny / L1-resident)
    const __half* up = g_uh + (size_t)p * (B_ * D1_);
    uint32_t bf[8][2];
    #pragma unroll
    for (int j = 0; j < 8; j++) {
        int b = j * 8 + r;
        bf[j][0] = *(const uint32_t*)(up + b * 16 + 2 * q);
        bf[j][1] = *(const uint32_t*)(up + b * 16 + 2 * q + 8);
    }

    const float* Wp = W + (size_t)p * (SD_ * D1_);
    for (int rt = 0; rt < 8; rt++) {
        int sd0 = wid * 128 + rt * 16;
        // A fragment: rows (sd0+r, sd0+r+8), k pairs (2q, 2q+8)
        const float* w0 = Wp + (size_t)(sd0 + r) * 16 + 2 * q;
        uint32_t a[4];
        {
            float2 f; __half2 h;
            f = *(const float2*)(w0);        h = __floats2half2_rn(f.x, f.y); a[0] = *(uint32_t*)&h;
            f = *(const float2*)(w0 + 128);  h = __floats2half2_rn(f.x, f.y); a[1] = *(uint32_t*)&h;  // row +8
            f = *(const float2*)(w0 + 8);    h = __floats2half2_rn(f.x, f.y); a[2] = *(uint32_t*)&h;  // k +8
            f = *(const float2*)(w0 + 136);  h = __floats2half2_rn(f.x, f.y); a[3] = *(uint32_t*)&h;
        }
        #pragma unroll
        for (int j = 0; j < 8; j++) {
            float d0, d1, d2, d3;
            asm volatile(
                "mma.sync.aligned.m16n8k16.row.col.f32.f16.f16.f32 "
                "{%0,%1,%2,%3}, {%4,%5,%6,%7}, {%8,%9}, {%10,%11,%12,%13};"
                : "=f"(d0), "=f"(d1), "=f"(d2), "=f"(d3)
                : "r"(a[0]), "r"(a[1]), "r"(a[2]), "r"(a[3]),
                  "r"(bf[j][0]), "r"(bf[j][1]),
                  "f"(0.f), "f"(0.f), "f"(0.f), "f"(0.f));
            __half2 lo = __floats2half2_rn(d0, d1);
            __half2 hi = __floats2half2_rn(d2, d3);
            int c = j * 8 + 2 * q;
            *(__half2*)&st[wid][ r      * ST_PITCH + c] = lo;
            *(__half2*)&st[wid][(r + 8) * ST_PITCH + c] = hi;
        }
        __syncwarp();
        // write 16 rows x 128B with STG.128
        #pragma unroll
        for (int i = 0; i < 4; i++) {
            int idx = i * 32 + lane;                 // 0..127
            int row = idx >> 3, c16 = idx & 7;
            uint4 v = *(const uint4*)&st[wid][row * ST_PITCH + c16 * 8];
            *(uint4*)(g_preds + ((size_t)p * SD_ + sd0 + row) * 64 + c16 * 8) = v;
        }
        __syncwarp();
    }
}

// ---------------- softmax over S ----------------
__global__ void softmax_kernel() {
    int p    = blockIdx.x * 8 + (threadIdx.x >> 5);
    int lane = threadIdx.x & 31;
    float x = g_logits[p * S_ + lane];
    float m = x;
    #pragma unroll
    for (int o = 16; o; o >>= 1) m = fmaxf(m, __shfl_xor_sync(0xffffffffu, m, o));
    float e = expf(x - m);
    float sum = e;
    #pragma unroll
    for (int o = 16; o; o >>= 1) sum += __shfl_xor_sync(0xffffffffu, sum, o);
    g_rw[p * S_ + lane] = e / sum;
}

// ---------------- ws[sd][b] = sum_p rw[p][s]*preds[p][sd][b] ----------------
__global__ void __launch_bounds__(256) ws_kernel() {
    int sdl  = threadIdx.x >> 5;               // 0..7
    int sd   = blockIdx.x * 8 + sdl;
    int s    = sd >> 5;
    int lane = threadIdx.x & 31;               // half2 index over b
    const int CP = P_ / 8;                     // 288 p per chunk
    int p0 = blockIdx.y * CP;
    const __half2* pp = (const __half2*)(g_preds + ((size_t)p0 * SD_ + sd) * 64) + lane;
    float2 acc = make_float2(0.f, 0.f);
    #pragma unroll 8
    for (int i = 0; i < CP; i++) {
        float w  = __ldg(&g_rw[(p0 + i) * S_ + s]);
        float2 h = ldcs_h2(pp + (size_t)i * (SD_ * 32));
        acc.x += w * h.x; acc.y += w * h.y;
    }
    atomicAdd(&g_ws[sd * 64 + lane * 2    ], acc.x);
    atomicAdd(&g_ws[sd * 64 + lane * 2 + 1], acc.y);
}

// ---------------- v = squash(ws) over D2 ----------------
__global__ void squash_v_kernel() {
    int gid = blockIdx.x * blockDim.x + threadIdx.x;   // 0..2047
    int s = gid >> 6, b = gid & 63;
    float x[32]; float sq = 0.f;
    #pragma unroll
    for (int d = 0; d < 32; d++) { x[d] = g_ws[(s * 32 + d) * B_ + b]; sq += x[d] * x[d]; }
    float sc = (sq / (1.f + sq)) / sqrtf(sq + EPSQ);
    #pragma unroll
    for (int d = 0; d < 32; d++) g_v[(s * 32 + d) * B_ + b] = x[d] * sc;
}

// ---------------- logits[p][s] += (1/B) sum_{d,b} preds*v ----------------
__global__ void agree_kernel() {
    int p    = blockIdx.x;
    int warp = threadIdx.x >> 5, lane = threadIdx.x & 31;
    #pragma unroll
    for (int si = 0; si < 4; si++) {
        int s = si * 8 + warp;
        const __half2* pp = (const __half2*)(g_preds + ((size_t)p * SD_ + s * D2_) * B_);
        const float2*  vp = (const float2*)(g_v + (size_t)(s * D2_) * B_);
        float acc = 0.f;
        #pragma unroll 8
        for (int d = 0; d < 32; d++) {
            float2 hf = ldcs_h2(pp + d * 32 + lane);
            float2 vv = __ldg(vp + d * 32 + lane);
            acc += hf.x * vv.x + hf.y * vv.y;
        }
        #pragma unroll
        for (int o = 16; o; o >>= 1) acc += __shfl_xor_sync(0xffffffffu, acc, o);
        if (lane == 0) g_logits[p * S_ + s] += acc * (1.f / 64.f);
    }
}

// ---------------- final squash -> out[b][s][d] ----------------
__global__ void final_kernel(float* __restrict__ out) {
    int gid = blockIdx.x * blockDim.x + threadIdx.x;
    int s = gid >> 6, b = gid & 63;
    float x[32]; float sq = 0.f;
    #pragma unroll
    for (int d = 0; d < 32; d++) { x[d] = g_ws[(s * 32 + d) * B_ + b]; sq += x[d] * x[d]; }
    float sc = (sq / (1.f + sq)) / sqrtf(sq + EPSQ);
    #pragma unroll
    for (int d = 0; d < 32; d++) out[(b * 32 + s) * 32 + d] = x[d] * sc;
}

// ---------------- launch ----------------
extern "C" void kernel_launch(void* const* d_in, const int* in_sizes, int n_in,
                              void* d_out, int out_size) {
    const float* caps = (const float*)d_in[0];   // [B,P,D1] fp32
    const float* W    = (const float*)d_in[1];   // [P,S,D2,D1] fp32
    float* out        = (float*)d_out;           // [B,1,S,D2] fp32

    zero_logits_kernel<<<(P_ * S_) / 256, 256>>>();
    squash_u_kernel<<<(P_ * B_) / 256, 256>>>(caps);
    preds_hmma_kernel<<<P_, 256>>>(W);

    for (int it = 0; it < 3; it++) {
        softmax_kernel<<<P_ / 8, 256>>>();
        zero_ws_kernel<<<(SD_ * B_) / 256, 256>>>();
        ws_kernel<<<dim3(SD_ / 8, 8), 256>>>();
        if (it < 2) {
            squash_v_kernel<<<8, 256>>>();
            agree_kernel<<<P_, 256>>>();
        } else {
            final_kernel<<<8, 256>>>(out);
        }
    }
}